// round 4
// baseline (speedup 1.0000x reference)
#include <cuda_runtime.h>
#include <cuda_bf16.h>
#include <cstdint>

// time_embeddings: out[b, i] = sin/cos(time[b] * 10000^(-(i//2)/640))
// B = 65536, DIM = 1280, fp32 out. HBM-write-bound (~335.5 MB out).
//
// Round-4: 256-bit stores (st.global.cs.v8.f32, sm_100a). Each thread owns
// 8 columns (4 pairs -> 4 angles) of one row; a 320-thread block covers TWO
// full rows per iteration (2 x 5120 B contiguous). Store-instruction count
// halves vs round-3; DRAM traffic unchanged. Grid 3552 keeps ~4-wave
// scheduling slack (round-3 lesson).

#define DIM      1280
#define CHUNK8S  (DIM / 8)     // 160 float8 per row
#define BLOCK    320           // 2 rows x 160 chunks per block-iteration
#define GRID     3552

__global__ __launch_bounds__(BLOCK, 6)
void time_emb_kernel(const float* __restrict__ time, float* __restrict__ out, int B)
{
    const int tid = threadIdx.x;
    const int sub = tid / CHUNK8S;          // 0 or 1: which row of the pair
    const int c8  = tid - sub * CHUNK8S;    // 0..159: float8 chunk in the row

    // rate(p) = 10000^(-p/640) = exp2(-log2(10000)/640 * p), p = i//2
    const float C = -13.287712379549449f / 640.0f;
    const int pb = 4 * c8;                  // first pair index of this chunk
    const float r0 = exp2f(C * (float)(pb + 0));
    const float r1 = exp2f(C * (float)(pb + 1));
    const float r2 = exp2f(C * (float)(pb + 2));
    const float r3 = exp2f(C * (float)(pb + 3));

    // Cody-Waite: 2*pi = HI + LO, HI=6.28125 exact for k<=160 (angle<=1000)
    const float INV2PI = 0.15915494309189535f;
    const float HI     = 6.28125f;
    const float LO     = 1.9353071795864769e-3f;

    const int stride = 2 * GRID;            // rows consumed per grid pass
    for (int row = 2 * blockIdx.x + sub; row < B; row += stride) {
        const float t = __ldg(&time[row]);

        float a0 = t * r0, a1 = t * r1, a2 = t * r2, a3 = t * r3;

        float k0 = rintf(a0 * INV2PI), k1 = rintf(a1 * INV2PI);
        float k2 = rintf(a2 * INV2PI), k3 = rintf(a3 * INV2PI);

        float x0 = fmaf(k0, -LO, fmaf(k0, -HI, a0));
        float x1 = fmaf(k1, -LO, fmaf(k1, -HI, a1));
        float x2 = fmaf(k2, -LO, fmaf(k2, -HI, a2));
        float x3 = fmaf(k3, -LO, fmaf(k3, -HI, a3));

        float s0, c0, s1, c1, s2, c2, s3, c3;
        __sincosf(x0, &s0, &c0);
        __sincosf(x1, &s1, &c1);
        __sincosf(x2, &s2, &c2);
        __sincosf(x3, &s3, &c3);

        // even col -> sin, odd col -> cos; cols 8*c8 .. 8*c8+7 of this row
        float* p = out + (size_t)row * DIM + 8 * c8;
        asm volatile(
            "st.global.cs.v8.f32 [%0], {%1, %2, %3, %4, %5, %6, %7, %8};"
            :: "l"(p),
               "f"(s0), "f"(c0), "f"(s1), "f"(c1),
               "f"(s2), "f"(c2), "f"(s3), "f"(c3)
            : "memory");
    }
}

extern "C" void kernel_launch(void* const* d_in, const int* in_sizes, int n_in,
                              void* d_out, int out_size)
{
    const float* time = (const float*)d_in[0];
    float* out = (float*)d_out;
    const int B = in_sizes[0];

    time_emb_kernel<<<GRID, BLOCK>>>(time, out, B);
}